// round 3
// baseline (speedup 1.0000x reference)
#include <cuda_runtime.h>

#define N_NODES 20000
#define FDIM    128
#define HDIM    256
#define E_EDGES 262144
#define T_TRIP  393216
#define OUTD    3
#define MBINS   100

#define BM 64
#define BN 128
#define BK 16

// Scratch ping-pong activation buffers (sized for the larger triplet path).
__device__ float g_bufA[(size_t)T_TRIP * HDIM];
__device__ float g_bufB[(size_t)T_TRIP * HDIM];

// ---------------------------------------------------------------------------
// Packed f32x2 helpers (Blackwell FFMA2: 2x scalar FFMA throughput).
// Guarded: falls back to 2x scalar fmaf if the target lacks .f32x2.
// ---------------------------------------------------------------------------
__device__ __forceinline__ unsigned long long fma2(unsigned long long a,
                                                   unsigned long long b,
                                                   unsigned long long c) {
#if defined(__CUDA_ARCH__) && (__CUDA_ARCH__ >= 1000)
    unsigned long long d;
    asm("fma.rn.f32x2 %0, %1, %2, %3;" : "=l"(d) : "l"(a), "l"(b), "l"(c));
    return d;
#else
    float2 fa, fb, fc;
    asm("mov.b64 {%0, %1}, %2;" : "=f"(fa.x), "=f"(fa.y) : "l"(a));
    asm("mov.b64 {%0, %1}, %2;" : "=f"(fb.x), "=f"(fb.y) : "l"(b));
    asm("mov.b64 {%0, %1}, %2;" : "=f"(fc.x), "=f"(fc.y) : "l"(c));
    fc.x = fmaf(fa.x, fb.x, fc.x);
    fc.y = fmaf(fa.y, fb.y, fc.y);
    unsigned long long d;
    asm("mov.b64 %0, {%1, %2};" : "=l"(d) : "f"(fc.x), "f"(fc.y));
    return d;
#endif
}

__device__ __forceinline__ unsigned long long bcast2(float x) {
    unsigned long long d;
    asm("mov.b64 %0, {%1, %1};" : "=l"(d) : "f"(x));
    return d;
}

__device__ __forceinline__ float2 unpack2(unsigned long long p) {
    float2 r;
    asm("mov.b64 {%0, %1}, %2;" : "=f"(r.x), "=f"(r.y) : "l"(p));
    return r;
}

__device__ __forceinline__ float silu_f(float x) {
    return x / (1.0f + __expf(-x));
}

// ---------------------------------------------------------------------------
// Shared GEMM inner tile: Xs[BK][BM] (K-major) x Ws[BK][BN] -> 4x8 per thread
// ---------------------------------------------------------------------------
__device__ __forceinline__ void gemm_tile(const float (*Xs)[BM],
                                          const float (*Ws)[BN],
                                          int ty, int tx,
                                          unsigned long long acc[4][4]) {
#pragma unroll
    for (int k = 0; k < BK; k++) {
        float4 av = *(const float4*)&Xs[k][ty * 4];
        unsigned long long pa0 = bcast2(av.x);
        unsigned long long pa1 = bcast2(av.y);
        unsigned long long pa2 = bcast2(av.z);
        unsigned long long pa3 = bcast2(av.w);
        ulonglong2 b01 = *(const ulonglong2*)&Ws[k][tx * 8];
        ulonglong2 b23 = *(const ulonglong2*)&Ws[k][tx * 8 + 4];

        acc[0][0] = fma2(pa0, b01.x, acc[0][0]);
        acc[0][1] = fma2(pa0, b01.y, acc[0][1]);
        acc[0][2] = fma2(pa0, b23.x, acc[0][2]);
        acc[0][3] = fma2(pa0, b23.y, acc[0][3]);
        acc[1][0] = fma2(pa1, b01.x, acc[1][0]);
        acc[1][1] = fma2(pa1, b01.y, acc[1][1]);
        acc[1][2] = fma2(pa1, b23.x, acc[1][2]);
        acc[1][3] = fma2(pa1, b23.y, acc[1][3]);
        acc[2][0] = fma2(pa2, b01.x, acc[2][0]);
        acc[2][1] = fma2(pa2, b01.y, acc[2][1]);
        acc[2][2] = fma2(pa2, b23.x, acc[2][2]);
        acc[2][3] = fma2(pa2, b23.y, acc[2][3]);
        acc[3][0] = fma2(pa3, b01.x, acc[3][0]);
        acc[3][1] = fma2(pa3, b01.y, acc[3][1]);
        acc[3][2] = fma2(pa3, b23.x, acc[3][2]);
        acc[3][3] = fma2(pa3, b23.y, acc[3][3]);
    }
}

__device__ __forceinline__ void store_tile_silu(float* __restrict__ Y,
                                                int row0, int n0,
                                                int ty, int tx,
                                                unsigned long long acc[4][4]) {
#pragma unroll
    for (int i = 0; i < 4; i++) {
        int row = row0 + ty * 4 + i;
        float v[8];
#pragma unroll
        for (int j = 0; j < 4; j++) {
            float2 p = unpack2(acc[i][j]);
            v[2 * j]     = silu_f(p.x);
            v[2 * j + 1] = silu_f(p.y);
        }
        float4* dst = (float4*)&Y[(size_t)row * HDIM + n0 + tx * 8];
        dst[0] = make_float4(v[0], v[1], v[2], v[3]);
        dst[1] = make_float4(v[4], v[5], v[6], v[7]);
    }
}

// ---------------------------------------------------------------------------
// Layer 0: fused gather + RBF + GEMM + silu.  MODE 0 = edges, 1 = triplets.
// ---------------------------------------------------------------------------
template <int MODE>
__global__ void __launch_bounds__(256, 2) l0_kernel(
    const float* __restrict__ h,
    const int* __restrict__ iA, const int* __restrict__ iB,
    const int* __restrict__ iC,
    const float* __restrict__ rA, const float* __restrict__ rB,
    const float* __restrict__ cosv, const float* __restrict__ sinv,
    const float* __restrict__ mu,
    const float* __restrict__ W,
    float* __restrict__ Y) {
    const int K  = (MODE == 0) ? 356 : 586;
    const int KT = (MODE == 0) ? 23 * BK : 37 * BK;  // padded K

    __shared__ float Xs[BK][BM];
    __shared__ float Ws[BK][BN];
    __shared__ float mu_s[MBINS];

    int t = threadIdx.x;
    int row0 = blockIdx.x * BM;
    int n0   = blockIdx.y * BN;
    if (t < MBINS) mu_s[t] = mu[t];

    int lm = t >> 2;          // X-load role: row within tile
    int lk = (t & 3) * 4;     // X-load role: k group
    int wk = t >> 4;          // W-load role: k row
    int wn = (t & 15) * 8;    // W-load role: n group
    int ty = t >> 4;          // compute role
    int tx = t & 15;

    int row = row0 + lm;
    const float* hA = h + (size_t)iA[row] * FDIM;
    const float* hB = h + (size_t)iB[row] * FDIM;
    const float* hC = (MODE == 1) ? (h + (size_t)iC[row] * FDIM) : h;
    float ra = rA[row];
    float rb = (MODE == 1) ? rB[row] : 0.0f;
    float cv = (MODE == 1) ? cosv[row] : 0.0f;
    float sv = (MODE == 1) ? sinv[row] : 0.0f;

    unsigned long long acc[4][4];
#pragma unroll
    for (int i = 0; i < 4; i++)
#pragma unroll
        for (int j = 0; j < 4; j++) acc[i][j] = 0ull;

    __syncthreads();  // mu_s ready

    for (int k0 = 0; k0 < KT; k0 += BK) {
        // Build virtual X tile
#pragma unroll
        for (int i = 0; i < 4; i++) {
            int k = k0 + lk + i;
            float v;
            if (MODE == 0) {
                if (k < 128)      v = hA[k];
                else if (k < 256) v = hB[k - 128];
                else if (k < 356) { float d = mu_s[k - 256] - ra; v = __expf(-10.0f * d * d); }
                else              v = 0.0f;
            } else {
                if (k < 128)      v = hA[k];
                else if (k < 256) v = hB[k - 128];
                else if (k < 384) v = hC[k - 256];
                else if (k < 484) { float d = mu_s[k - 384] - ra; v = __expf(-10.0f * d * d); }
                else if (k < 584) { float d = mu_s[k - 484] - rb; v = __expf(-10.0f * d * d); }
                else if (k == 584) v = cv;
                else if (k == 585) v = sv;
                else               v = 0.0f;
            }
            Xs[lk + i][lm] = v;
        }
        // Load W tile (zero-pad rows >= K)
        int kw = k0 + wk;
        float4 w0, w1;
        if (kw < K) {
            const float4* wp = (const float4*)(W + (size_t)kw * HDIM + n0 + wn);
            w0 = wp[0];
            w1 = wp[1];
        } else {
            w0 = make_float4(0.f, 0.f, 0.f, 0.f);
            w1 = w0;
        }
        *(float4*)&Ws[wk][wn]     = w0;
        *(float4*)&Ws[wk][wn + 4] = w1;
        __syncthreads();
        gemm_tile(Xs, Ws, ty, tx, acc);
        __syncthreads();
    }
    store_tile_silu(Y, row0, n0, ty, tx, acc);
}

// ---------------------------------------------------------------------------
// Mid layers: Y = silu(X @ W),  X:[rows,256], W:[256,256]
// ---------------------------------------------------------------------------
__global__ void __launch_bounds__(256, 2) mid_kernel(const float* __restrict__ X,
                                                     const float* __restrict__ W,
                                                     float* __restrict__ Y) {
    __shared__ float Xs[BK][BM];
    __shared__ float Ws[BK][BN];

    int t = threadIdx.x;
    int row0 = blockIdx.x * BM;
    int n0   = blockIdx.y * BN;

    int lm = t >> 2, lk = (t & 3) * 4;
    int wk = t >> 4, wn = (t & 15) * 8;
    int ty = t >> 4, tx = t & 15;

    unsigned long long acc[4][4];
#pragma unroll
    for (int i = 0; i < 4; i++)
#pragma unroll
        for (int j = 0; j < 4; j++) acc[i][j] = 0ull;

    const float* xptr = X + (size_t)(row0 + lm) * HDIM + lk;
    const float* wptr = W + (size_t)wk * HDIM + n0 + wn;

    for (int k0 = 0; k0 < HDIM; k0 += BK) {
        float4 xv = *(const float4*)(xptr + k0);
        Xs[lk + 0][lm] = xv.x;
        Xs[lk + 1][lm] = xv.y;
        Xs[lk + 2][lm] = xv.z;
        Xs[lk + 3][lm] = xv.w;
        const float4* wp = (const float4*)(wptr + (size_t)k0 * HDIM);
        float4 w0 = wp[0], w1 = wp[1];
        *(float4*)&Ws[wk][wn]     = w0;
        *(float4*)&Ws[wk][wn + 4] = w1;
        __syncthreads();
        gemm_tile(Xs, Ws, ty, tx, acc);
        __syncthreads();
    }
    store_tile_silu(Y, row0, n0, ty, tx, acc);
}

// ---------------------------------------------------------------------------
// Output layer: out = X @ W3 + b3, W3:[256,3].  One warp per row.
// ---------------------------------------------------------------------------
__global__ void __launch_bounds__(256) out_kernel(const float* __restrict__ X,
                                                  const float* __restrict__ W3,
                                                  const float* __restrict__ b3,
                                                  float* __restrict__ out) {
    __shared__ float Ws[HDIM * OUTD];
    int t = threadIdx.x;
    for (int i = t; i < HDIM * OUTD; i += 256) Ws[i] = W3[i];
    __syncthreads();

    int row  = blockIdx.x * 8 + (t >> 5);
    int lane = t & 31;
    const float* xr = X + (size_t)row * HDIM;
    float s0 = 0.f, s1 = 0.f, s2 = 0.f;
#pragma unroll
    for (int k = lane; k < HDIM; k += 32) {
        float x = xr[k];
        s0 = fmaf(x, Ws[k * 3 + 0], s0);
        s1 = fmaf(x, Ws[k * 3 + 1], s1);
        s2 = fmaf(x, Ws[k * 3 + 2], s2);
    }
#pragma unroll
    for (int o = 16; o; o >>= 1) {
        s0 += __shfl_down_sync(0xffffffffu, s0, o);
        s1 += __shfl_down_sync(0xffffffffu, s1, o);
        s2 += __shfl_down_sync(0xffffffffu, s2, o);
    }
    if (lane == 0) {
        out[(size_t)row * 3 + 0] = s0 + b3[0];
        out[(size_t)row * 3 + 1] = s1 + b3[1];
        out[(size_t)row * 3 + 2] = s2 + b3[2];
    }
}

// ---------------------------------------------------------------------------
extern "C" void kernel_launch(void* const* d_in, const int* in_sizes, int n_in,
                              void* d_out, int out_size) {
    const float* h     = (const float*)d_in[0];
    const int*   src   = (const int*)d_in[1];
    const int*   dst   = (const int*)d_in[2];
    const float* enorm = (const float*)d_in[3];
    const int*   tsrc  = (const int*)d_in[4];
    const int*   tdi   = (const int*)d_in[5];
    const int*   tdj   = (const int*)d_in[6];
    const float* nij   = (const float*)d_in[7];
    const float* nik   = (const float*)d_in[8];
    const float* cosv  = (const float*)d_in[9];
    const float* sinv  = (const float*)d_in[10];
    const float* mu    = (const float*)d_in[11];
    const float* eW0   = (const float*)d_in[12];
    const float* eW1   = (const float*)d_in[13];
    const float* eW2   = (const float*)d_in[14];
    const float* eW3   = (const float*)d_in[15];
    const float* eb3   = (const float*)d_in[16];
    const float* tW0   = (const float*)d_in[17];
    const float* tW1   = (const float*)d_in[18];
    const float* tW2   = (const float*)d_in[19];
    const float* tW3   = (const float*)d_in[20];
    const float* tb3   = (const float*)d_in[21];
    float* out = (float*)d_out;

    float *bufA, *bufB;
    cudaGetSymbolAddress((void**)&bufA, g_bufA);
    cudaGetSymbolAddress((void**)&bufB, g_bufB);

    dim3 g_e(E_EDGES / BM, HDIM / BN);
    dim3 g_t(T_TRIP / BM, HDIM / BN);

    // Edge path
    l0_kernel<0><<<g_e, 256>>>(h, src, dst, nullptr, enorm, nullptr, nullptr,
                               nullptr, mu, eW0, bufA);
    mid_kernel<<<g_e, 256>>>(bufA, eW1, bufB);
    mid_kernel<<<g_e, 256>>>(bufB, eW2, bufA);
    out_kernel<<<E_EDGES / 8, 256>>>(bufA, eW3, eb3, out);

    // Triplet path
    l0_kernel<1><<<g_t, 256>>>(h, tsrc, tdi, tdj, nij, nik, cosv, sinv, mu,
                               tW0, bufA);
    mid_kernel<<<g_t, 256>>>(bufA, tW1, bufB);
    mid_kernel<<<g_t, 256>>>(bufB, tW2, bufA);
    out_kernel<<<T_TRIP / 8, 256>>>(bufA, tW3, tb3, out + (size_t)E_EDGES * 3);
}

// round 5
// speedup vs baseline: 3.3783x; 3.3783x over previous
#include <cuda_runtime.h>
#include <cuda_bf16.h>
#include <cstdint>

#define FDIM 128
#define HDIM 256
#define E_EDGES 262144
#define T_TRIP 393216
#define MBINS 100
#define KP_E0 384
#define KP_T0 640
#define KP_MID 256

// GEMM: CTA 128x128, K-chunk 64, 2 stages. Stage = 4 x 16KB (Ahi,Amid,Bhi,Bmid).
#define SA_HI 0
#define SA_MID (16 * 1024)
#define SB_HI (32 * 1024)
#define SB_MID (48 * 1024)
#define STAGE_BYTES (64 * 1024)
#define SMEM_GEMM (2 * STAGE_BYTES)

__device__ __nv_bfloat16 g_in_hi[(size_t)T_TRIP * KP_T0];
__device__ __nv_bfloat16 g_in_mid[(size_t)T_TRIP * KP_T0];
__device__ __nv_bfloat16 g_x_hi[(size_t)T_TRIP * HDIM];
__device__ __nv_bfloat16 g_x_mid[(size_t)T_TRIP * HDIM];
__device__ __nv_bfloat16 g_y_hi[(size_t)T_TRIP * HDIM];
__device__ __nv_bfloat16 g_y_mid[(size_t)T_TRIP * HDIM];
#define OFF_E0 0
#define OFF_E1 98304
#define OFF_E2 163840
#define OFF_T0 229376
#define OFF_T1 393216
#define OFF_T2 458752
__device__ __nv_bfloat16 g_w_hi[524288];
__device__ __nv_bfloat16 g_w_mid[524288];

__device__ __forceinline__ uint32_t smem_u32(const void* p) {
    uint32_t a;
    asm("{ .reg .u64 t; cvta.to.shared.u64 t, %1; cvt.u32.u64 %0, t; }" : "=r"(a) : "l"(p));
    return a;
}
__device__ __forceinline__ void cp16(uint32_t d, const void* s) {
    asm volatile("cp.async.cg.shared.global [%0], [%1], 16;" :: "r"(d), "l"(s));
}
#define CP_COMMIT() asm volatile("cp.async.commit_group;" ::: "memory")
#define CP_WAIT0() asm volatile("cp.async.wait_group 0;" ::: "memory")
#define CP_WAIT1() asm volatile("cp.async.wait_group 1;" ::: "memory")
#define LDSM4(r0, r1, r2, r3, a) \
    asm volatile("ldmatrix.sync.aligned.m8n8.x4.shared.b16 {%0,%1,%2,%3}, [%4];" \
                 : "=r"(r0), "=r"(r1), "=r"(r2), "=r"(r3) : "r"(a))

__device__ __forceinline__ void mma_bf16(float c[4], const uint32_t a[4], const uint32_t b[2]) {
    asm volatile(
        "mma.sync.aligned.m16n8k16.row.col.f32.bf16.bf16.f32 "
        "{%0,%1,%2,%3}, {%4,%5,%6,%7}, {%8,%9}, {%0,%1,%2,%3};"
        : "+f"(c[0]), "+f"(c[1]), "+f"(c[2]), "+f"(c[3])
        : "r"(a[0]), "r"(a[1]), "r"(a[2]), "r"(a[3]), "r"(b[0]), "r"(b[1]));
}
__device__ __forceinline__ float silu_f(float x) { return x / (1.0f + __expf(-x)); }
__device__ __forceinline__ uint32_t pkbf2(__nv_bfloat16 a, __nv_bfloat16 b) {
    __nv_bfloat162 v(a, b);
    return *reinterpret_cast<uint32_t*>(&v);
}
// silu -> (hi, mid) packed pair for two values; writes one u32 each to hi/mid streams
__device__ __forceinline__ void silu_split2(float v0, float v1, uint32_t* oh, uint32_t* om) {
    float a0 = silu_f(v0), a1 = silu_f(v1);
    __nv_bfloat16 h0 = __float2bfloat16_rn(a0), h1 = __float2bfloat16_rn(a1);
    *oh = pkbf2(h0, h1);
    *om = pkbf2(__float2bfloat16_rn(a0 - __bfloat162float(h0)),
                __float2bfloat16_rn(a1 - __bfloat162float(h1)));
}

// Load one K-chunk (64 bf16 = 128B) of A[128 rows] + B[128 rows], both limbs.
__device__ __forceinline__ void load_chunk(uint32_t stage, int t, size_t koff,
                                           const char* aH, const char* aM,
                                           const char* bH, const char* bM, size_t ldb) {
#pragma unroll
    for (int i = 0; i < 4; i++) {
        int idx = t + i * 256;
        int r = idx >> 3, c16 = idx & 7;
        uint32_t doff = r * 128 + ((c16 ^ (r & 7)) << 4);
        size_t soff = (size_t)r * ldb + koff + c16 * 16;
        cp16(stage + SA_HI + doff, aH + soff);
        cp16(stage + SA_MID + doff, aM + soff);
        cp16(stage + SB_HI + doff, bH + soff);
        cp16(stage + SB_MID + doff, bM + soff);
    }
    CP_COMMIT();
}

__global__ void prep_w_kernel(const float* __restrict__ W, int K, int KP,
                              __nv_bfloat16* __restrict__ hi, __nv_bfloat16* __restrict__ mid) {
    int idx = blockIdx.x * 256 + threadIdx.x;
    int n = idx / KP, k = idx % KP;
    float v = (k < K) ? W[(size_t)k * HDIM + n] : 0.0f;
    __nv_bfloat16 h = __float2bfloat16_rn(v);
    hi[idx] = h;
    mid[idx] = __float2bfloat16_rn(v - __bfloat162float(h));
}

template <int MODE>
__global__ void __launch_bounds__(256) gather_kernel(
    const float* __restrict__ h, const int* __restrict__ iA, const int* __restrict__ iB,
    const int* __restrict__ iC, const float* __restrict__ rA, const float* __restrict__ rB,
    const float* __restrict__ cosv, const float* __restrict__ sinv, const float* __restrict__ mu,
    __nv_bfloat16* __restrict__ Ghi, __nv_bfloat16* __restrict__ Gmid) {
    const int KP = MODE ? KP_T0 : KP_E0;
    __shared__ float mu_s[MBINS];
    int t = threadIdx.x;
    if (t < MBINS) mu_s[t] = mu[t];
    __syncthreads();
    int w = t >> 5, lane = t & 31;
    int row = blockIdx.x * 8 + w;
    const float* hA = h + (size_t)iA[row] * FDIM;
    const float* hB = h + (size_t)iB[row] * FDIM;
    const float* hC = (MODE == 1) ? (h + (size_t)iC[row] * FDIM) : h;
    float ra = rA[row];
    float rb = (MODE == 1) ? rB[row] : 0.0f;
    float cv = (MODE == 1) ? cosv[row] : 0.0f;
    float sv = (MODE == 1) ? sinv[row] : 0.0f;
    __nv_bfloat16* oh = Ghi + (size_t)row * KP;
    __nv_bfloat16* om = Gmid + (size_t)row * KP;
    for (int k = lane; k < KP; k += 32) {
        float v;
        if (MODE == 0) {
            if (k < 128)      v = hA[k];
            else if (k < 256) v = hB[k - 128];
            else if (k < 356) { float d = mu_s[k - 256] - ra; v = __expf(-10.0f * d * d); }
            else              v = 0.0f;
        } else {
            if (k < 128)      v = hA[k];
            else if (k < 256) v = hB[k - 128];
            else if (k < 384) v = hC[k - 256];
            else if (k < 484) { float d = mu_s[k - 384] - ra; v = __expf(-10.0f * d * d); }
            else if (k < 584) { float d = mu_s[k - 484] - rb; v = __expf(-10.0f * d * d); }
            else if (k == 584) v = cv;
            else if (k == 585) v = sv;
            else               v = 0.0f;
        }
        __nv_bfloat16 hh = __float2bfloat16_rn(v);
        oh[k] = hh;
        om[k] = __float2bfloat16_rn(v - __bfloat162float(hh));
    }
}

// C = silu(A @ B^T), 2-limb bf16 via mma.sync m16n8k16.
// A:[rows,ld], B:[256,ld]. Grid: (2 N-halves fastest, rows/128). 256 threads.
__global__ void __launch_bounds__(256, 1) gemm_kernel(
    const __nv_bfloat16* __restrict__ Ahi, const __nv_bfloat16* __restrict__ Amid,
    const __nv_bfloat16* __restrict__ Bhi, const __nv_bfloat16* __restrict__ Bmid,
    int ld, int nchunks, __nv_bfloat16* __restrict__ Chi, __nv_bfloat16* __restrict__ Cmid) {
    extern __shared__ char smem[];
    uint32_t sb = smem_u32(smem);
    int t = threadIdx.x, lane = t & 31, w = t >> 5;
    int row0 = blockIdx.y * 128, n0cta = blockIdx.x * 128;
    int wm = (w & 3) * 32, wn = (w >> 2) * 64;

    const char* aH = (const char*)(Ahi + (size_t)row0 * ld);
    const char* aM = (const char*)(Amid + (size_t)row0 * ld);
    const char* bH = (const char*)(Bhi + (size_t)n0cta * ld);
    const char* bM = (const char*)(Bmid + (size_t)n0cta * ld);
    const size_t ldb = (size_t)ld * 2;

    float acc[2][8][4];
#pragma unroll
    for (int i = 0; i < 2; i++)
#pragma unroll
        for (int j = 0; j < 8; j++)
#pragma unroll
            for (int q = 0; q < 4; q++) acc[i][j][q] = 0.0f;

    // lane roles for ldmatrix
    int a_row = (lane & 15);          // row within m16 tile
    int a_kh = lane >> 4;             // k half (0/1 -> +0/+8)
    int b_row = (lane & 7) + ((lane >> 4) << 3);  // row within n16 pair
    int b_kh = (lane >> 3) & 1;

    load_chunk(sb, t, 0, aH, aM, bH, bM, ldb);

    for (int c = 0; c < nchunks; c++) {
        int nxt = c + 1;
        if (nxt < nchunks) {
            load_chunk(sb + (nxt & 1) * STAGE_BYTES, t, (size_t)nxt * 128, aH, aM, bH, bM, ldb);
            CP_WAIT1();
        } else {
            CP_WAIT0();
        }
        __syncthreads();
        uint32_t stage = sb + (c & 1) * STAGE_BYTES;
#pragma unroll
        for (int ks = 0; ks < 4; ks++) {
            uint32_t aHf[2][4], aMf[2][4], bHf[8][2], bMf[8][2];
#pragma unroll
            for (int mt = 0; mt < 2; mt++) {
                int r = wm + mt * 16 + a_row;
                uint32_t off = r * 128 + (((ks * 2 + a_kh) ^ (r & 7)) << 4);
                LDSM4(aHf[mt][0], aHf[mt][1], aHf[mt][2], aHf[mt][3], stage + SA_HI + off);
                LDSM4(aMf[mt][0], aMf[mt][1], aMf[mt][2], aMf[mt][3], stage + SA_MID + off);
            }
#pragma unroll
            for (int np = 0; np < 4; np++) {
                int r = wn + np * 16 + b_row;
                uint32_t off = r * 128 + (((ks * 2 + b_kh) ^ (r & 7)) << 4);
                uint32_t r0, r1, r2, r3;
                LDSM4(r0, r1, r2, r3, stage + SB_HI + off);
                bHf[np * 2][0] = r0; bHf[np * 2][1] = r1;
                bHf[np * 2 + 1][0] = r2; bHf[np * 2 + 1][1] = r3;
                LDSM4(r0, r1, r2, r3, stage + SB_MID + off);
                bMf[np * 2][0] = r0; bMf[np * 2][1] = r1;
                bMf[np * 2 + 1][0] = r2; bMf[np * 2 + 1][1] = r3;
            }
#pragma unroll
            for (int mt = 0; mt < 2; mt++)
#pragma unroll
                for (int nt = 0; nt < 8; nt++) {
                    mma_bf16(acc[mt][nt], aHf[mt], bHf[nt]);
                    mma_bf16(acc[mt][nt], aHf[mt], bMf[nt]);
                    mma_bf16(acc[mt][nt], aMf[mt], bHf[nt]);
                }
        }
        __syncthreads();
    }

    // Epilogue: silu + limb split. c0,c1 @ (m=lane>>2, n=2*(lane&3)); c2,c3 @ m+8.
    int mrow = lane >> 2, ncol = (lane & 3) * 2;
#pragma unroll
    for (int mt = 0; mt < 2; mt++) {
#pragma unroll
        for (int nt = 0; nt < 8; nt++) {
            int r = row0 + wm + mt * 16 + mrow;
            int cc = n0cta + wn + nt * 8 + ncol;
            uint32_t oh, om;
            silu_split2(acc[mt][nt][0], acc[mt][nt][1], &oh, &om);
            *(uint32_t*)(Chi + (size_t)r * HDIM + cc) = oh;
            *(uint32_t*)(Cmid + (size_t)r * HDIM + cc) = om;
            silu_split2(acc[mt][nt][2], acc[mt][nt][3], &oh, &om);
            *(uint32_t*)(Chi + (size_t)(r + 8) * HDIM + cc) = oh;
            *(uint32_t*)(Cmid + (size_t)(r + 8) * HDIM + cc) = om;
        }
    }
}

__global__ void __launch_bounds__(256) out_kernel(
    const __nv_bfloat16* __restrict__ Xhi, const __nv_bfloat16* __restrict__ Xmid,
    const float* __restrict__ W3, const float* __restrict__ b3, float* __restrict__ out) {
    __shared__ float Ws[HDIM * 3];
    int t = threadIdx.x;
    for (int i = t; i < HDIM * 3; i += 256) Ws[i] = W3[i];
    __syncthreads();
    int row = blockIdx.x * 8 + (t >> 5);
    int lane = t & 31;
    const uint32_t* ph = (const uint32_t*)Xhi + (size_t)row * 128;
    const uint32_t* pm = (const uint32_t*)Xmid + (size_t)row * 128;
    float s0 = 0.f, s1 = 0.f, s2 = 0.f;
#pragma unroll
    for (int i = 0; i < 4; i++) {
        uint32_t uh = ph[lane + i * 32], um = pm[lane + i * 32];
        __nv_bfloat162 bh = *reinterpret_cast<__nv_bfloat162*>(&uh);
        __nv_bfloat162 bm = *reinterpret_cast<__nv_bfloat162*>(&um);
        float x0 = __bfloat162float(bh.x) + __bfloat162float(bm.x);
        float x1 = __bfloat162float(bh.y) + __bfloat162float(bm.y);
        int k = 2 * (lane + i * 32);
        s0 = fmaf(x0, Ws[k * 3 + 0], s0); s1 = fmaf(x0, Ws[k * 3 + 1], s1);
        s2 = fmaf(x0, Ws[k * 3 + 2], s2);
        s0 = fmaf(x1, Ws[k * 3 + 3], s0); s1 = fmaf(x1, Ws[k * 3 + 4], s1);
        s2 = fmaf(x1, Ws[k * 3 + 5], s2);
    }
#pragma unroll
    for (int o = 16; o; o >>= 1) {
        s0 += __shfl_down_sync(0xffffffffu, s0, o);
        s1 += __shfl_down_sync(0xffffffffu, s1, o);
        s2 += __shfl_down_sync(0xffffffffu, s2, o);
    }
    if (lane == 0) {
        out[(size_t)row * 3 + 0] = s0 + b3[0];
        out[(size_t)row * 3 + 1] = s1 + b3[1];
        out[(size_t)row * 3 + 2] = s2 + b3[2];
    }
}

extern "C" void kernel_launch(void* const* d_in, const int* in_sizes, int n_in,
                              void* d_out, int out_size) {
    const float* h = (const float*)d_in[0];
    const int* src = (const int*)d_in[1];
    const int* dst = (const int*)d_in[2];
    const float* enorm = (const float*)d_in[3];
    const int* tsrc = (const int*)d_in[4];
    const int* tdi = (const int*)d_in[5];
    const int* tdj = (const int*)d_in[6];
    const float* nij = (const float*)d_in[7];
    const float* nik = (const float*)d_in[8];
    const float* cosv = (const float*)d_in[9];
    const float* sinv = (const float*)d_in[10];
    const float* mu = (const float*)d_in[11];
    const float* eW0 = (const float*)d_in[12];
    const float* eW1 = (const float*)d_in[13];
    const float* eW2 = (const float*)d_in[14];
    const float* eW3 = (const float*)d_in[15];
    const float* eb3 = (const float*)d_in[16];
    const float* tW0 = (const float*)d_in[17];
    const float* tW1 = (const float*)d_in[18];
    const float* tW2 = (const float*)d_in[19];
    const float* tW3 = (const float*)d_in[20];
    const float* tb3 = (const float*)d_in[21];
    float* out = (float*)d_out;

    __nv_bfloat16 *inH, *inM, *xH, *xM, *yH, *yM, *wH, *wM;
    cudaGetSymbolAddress((void**)&inH, g_in_hi);
    cudaGetSymbolAddress((void**)&inM, g_in_mid);
    cudaGetSymbolAddress((void**)&xH, g_x_hi);
    cudaGetSymbolAddress((void**)&xM, g_x_mid);
    cudaGetSymbolAddress((void**)&yH, g_y_hi);
    cudaGetSymbolAddress((void**)&yM, g_y_mid);
    cudaGetSymbolAddress((void**)&wH, g_w_hi);
    cudaGetSymbolAddress((void**)&wM, g_w_mid);

    cudaFuncSetAttribute(gemm_kernel, cudaFuncAttributeMaxDynamicSharedMemorySize, SMEM_GEMM);

    prep_w_kernel<<<KP_E0, 256>>>(eW0, 356, KP_E0, wH + OFF_E0, wM + OFF_E0);
    prep_w_kernel<<<KP_MID, 256>>>(eW1, 256, KP_MID, wH + OFF_E1, wM + OFF_E1);
    prep_w_kernel<<<KP_MID, 256>>>(eW2, 256, KP_MID, wH + OFF_E2, wM + OFF_E2);
    prep_w_kernel<<<KP_T0, 256>>>(tW0, 586, KP_T0, wH + OFF_T0, wM + OFF_T0);
    prep_w_kernel<<<KP_MID, 256>>>(tW1, 256, KP_MID, wH + OFF_T1, wM + OFF_T1);
    prep_w_kernel<<<KP_MID, 256>>>(tW2, 256, KP_MID, wH + OFF_T2, wM + OFF_T2);

    dim3 ge(2, E_EDGES / 128), gt(2, T_TRIP / 128);

    gather_kernel<0><<<E_EDGES / 8, 256>>>(h, src, dst, nullptr, enorm, nullptr,
                                           nullptr, nullptr, mu, inH, inM);
    gemm_kernel<<<ge, 256, SMEM_GEMM>>>(inH, inM, wH + OFF_E0, wM + OFF_E0, KP_E0, 6, xH, xM);
    gemm_kernel<<<ge, 256, SMEM_GEMM>>>(xH, xM, wH + OFF_E1, wM + OFF_E1, KP_MID, 4, yH, yM);
    gemm_kernel<<<ge, 256, SMEM_GEMM>>>(yH, yM, wH + OFF_E2, wM + OFF_E2, KP_MID, 4, xH, xM);
    out_kernel<<<E_EDGES / 8, 256>>>(xH, xM, eW3, eb3, out);

    gather_kernel<1><<<T_TRIP / 8, 256>>>(h, tsrc, tdi, tdj, nij, nik, cosv, sinv, mu, inH, inM);
    gemm_kernel<<<gt, 256, SMEM_GEMM>>>(inH, inM, wH + OFF_T0, wM + OFF_T0, KP_T0, 10, xH, xM);
    gemm_kernel<<<gt, 256, SMEM_GEMM>>>(xH, xM, wH + OFF_T1, wM + OFF_T1, KP_MID, 4, yH, yM);
    gemm_kernel<<<gt, 256, SMEM_GEMM>>>(yH, yM, wH + OFF_T2, wM + OFF_T2, KP_MID, 4, xH, xM);
    out_kernel<<<T_TRIP / 8, 256>>>(xH, xM, tW3, tb3, out + (size_t)E_EDGES * 3);
}